// round 4
// baseline (speedup 1.0000x reference)
#include <cuda_runtime.h>
#include <cstdint>

// Problem constants
#define NCTA      96     // persistent CTAs (<= 148 SMs, all co-resident)
#define NTHREADS  256    // 8 warps — R1-proven best occupancy/register balance
#define BB        16     // batch
#define TT        1024   // time steps
#define DD        768    // hidden dim
#define NGATES    4
#define DPC       8      // d-columns per CTA (96*8 = 768)
#define GC        32     // gate columns per CTA (4 gates * 8 d)
#define NW        8      // warps per CTA
#define NSLICE    16     // k-slices = 8 warps x 2 half-warps
#define KS        48     // k per half-warp slice (16*48 = 768)
#define KS2       24     // packed f32x2 k-pairs per slice

// Global exchange state (device globals: no allocation anywhere)
__device__ __align__(16) float    g_hbuf[2][BB * DD];
__device__ unsigned               g_flags[NCTA];

static __device__ __forceinline__ unsigned long long pack2(float x, float y) {
    unsigned long long r;
    asm("mov.b64 %0, {%1, %2};" : "=l"(r) : "f"(x), "f"(y));
    return r;
}
static __device__ __forceinline__ void fma2(unsigned long long& d,
                                            unsigned long long a,
                                            unsigned long long b) {
    // Packed dual-FMA (Blackwell f32x2) — 2x FFMA throughput vs scalar.
    asm("fma.rn.f32x2 %0, %1, %2, %0;" : "+l"(d) : "l"(a), "l"(b));
}
static __device__ __forceinline__ float2 unpack2(unsigned long long v) {
    float lo, hi;
    asm("mov.b64 {%0, %1}, %2;" : "=f"(lo), "=f"(hi) : "l"(v));
    return make_float2(lo, hi);
}

// Zero the barrier flags before each run (graph replays reuse device globals).
__global__ void rnn_reset_kernel() {
    if (threadIdx.x < NCTA) g_flags[threadIdx.x] = 0u;
}

__global__ void __launch_bounds__(NTHREADS, 1)
rnn_persistent_kernel(const float* __restrict__ states,
                      const float* __restrict__ Wx,
                      const float* __restrict__ R,
                      const float* __restrict__ bias,
                      float* __restrict__ out)
{
    // Dynamic smem = 48KB (h panel). Reduction scratch ALIASES the h panel:
    // h is dead after the GEMM phase (S2 syncthreads guards it).
    extern __shared__ float smem[];
    float* h_sm = smem;                       // [BB][DD] = 12288 floats (ph 2-3)
    float* red  = smem;                       // [NSLICE][BB][GC] = 8192 (ph 4-5)
    float* gsm  = smem + NSLICE * BB * GC;    // [BB][GC] = 512 floats   (ph 5-6)

    const int tid = threadIdx.x;
    const int cta = blockIdx.x;
    const int w   = tid >> 5;        // warp id (0..7)
    const int l   = tid & 31;        // lane
    const int hw  = l >> 4;          // half-warp (0/1) -> k sub-slice
    const int c   = l & 15;          // column pair index (0..15)
    const int sl  = (w << 1) | hw;   // k-slice id (0..15)
    const int kb  = sl * KS;         // k base for this slice
    const int colA = c;              // CTA-local gate column (gates 0,1)
    const int colB = c + 16;         // CTA-local gate column (gates 2,3)
    const int d0  = cta * DPC;

    // ---- One-time: R slices for BOTH columns into registers (k-pair packed).
    // Each h load then feeds 4 FFMA2 (2 cols x 2 k-pairs): LDS count halved.
    unsigned long long RA[KS2], RB[KS2];   // 96 registers
    {
        const int ggA = colA >> 3, dlA = colA & 7;
        const int ggB = colB >> 3, dlB = colB & 7;
        const float* RgA = R + (size_t)ggA * DD * DD + (size_t)(d0 + dlA);
        const float* RgB = R + (size_t)ggB * DD * DD + (size_t)(d0 + dlB);
        #pragma unroll
        for (int j = 0; j < KS2; ++j) {
            RA[j] = pack2(RgA[(size_t)(kb + 2 * j) * DD],
                          RgA[(size_t)(kb + 2 * j + 1) * DD]);
            RB[j] = pack2(RgB[(size_t)(kb + 2 * j) * DD],
                          RgB[(size_t)(kb + 2 * j + 1) * DD]);
        }
    }

    // ---- One-time: per-cell state (c), biases, and t=0 output row. ----
    float c_state = 0.f, b_i = 0.f, b_f = 0.f, b_z = 0.f, b_o = 0.f;
    int cb = 0, cd = 0;
    if (tid < BB * DPC) {                         // 128 "cell" threads
        cb = tid >> 3;                            // batch
        cd = tid & 7;                             // local d
        const int d = d0 + cd;
        b_i = bias[0 * DD + d];
        b_f = bias[1 * DD + d];
        b_z = bias[2 * DD + d];
        b_o = bias[3 * DD + d];
        const float h0 = states[(size_t)(0 * BB + cb) * DD + d];
        c_state        = states[(size_t)(1 * BB + cb) * DD + d];
        // out layout: [2][B][T+1][NH=1][D]; row t=0 is the initial state.
        out[((size_t)(0 * BB + cb) * (TT + 1) + 0) * DD + d] = h0;
        out[((size_t)(1 * BB + cb) * (TT + 1) + 0) * DD + d] = c_state;
    }

    // ---- Main recurrence ----
    for (int t = 0; t < TT; ++t) {
        // Phase 1: issue Wx(t) loads early (hidden behind GEMM).
        float wxi = 0.f, wxf = 0.f, wxz = 0.f, wxo = 0.f;
        if (tid < BB * DPC) {
            const float* wp = Wx + ((size_t)cb * TT + t) * (NGATES * DD) + (d0 + cd);
            wxi = wp[0 * DD];
            wxf = wp[1 * DD];
            wxz = wp[2 * DD];
            wxo = wp[3 * DD];
        }

        // Phase 2: load h(t) panel [16 x 768] into smem (coalesced float4).
        {
            const float* src = (t == 0) ? states : g_hbuf[t & 1];
            const float4* s4 = (const float4*)src;
            float4* d4 = (float4*)h_sm;
            #pragma unroll
            for (int r = 0; r < (BB * DD / 4) / NTHREADS; ++r)   // 12 iters
                d4[tid + r * NTHREADS] = s4[tid + r * NTHREADS];
        }
        __syncthreads();   // S1: h panel ready

        // Phase 3: GEMM. Half-warp owns 48-k slice; lane owns 2 gate columns.
        // One LDS.128 (4 h values, half-warp broadcast) feeds 4 FFMA2.
        unsigned long long accA[BB], accB[BB];    // 64 registers
        #pragma unroll
        for (int b = 0; b < BB; ++b) { accA[b] = 0ull; accB[b] = 0ull; }
        {
            const float* hk = h_sm + kb;
            #pragma unroll
            for (int j = 0; j < KS2; j += 2) {    // 12 iters, 4 k's each
                #pragma unroll
                for (int b = 0; b < BB; ++b) {
                    const ulonglong2 hh =
                        *(const ulonglong2*)(hk + (size_t)b * DD + 2 * j);
                    fma2(accA[b], hh.x, RA[j]);
                    fma2(accA[b], hh.y, RA[j + 1]);
                    fma2(accB[b], hh.x, RB[j]);
                    fma2(accB[b], hh.y, RB[j + 1]);
                }
            }
        }
        __syncthreads();   // S2: all warps done reading h_sm (red aliases it!)

        // Phase 4: spill per-slice partials red[sl][b][gc] (fold even/odd k).
        {
            float* rw = red + (size_t)sl * (BB * GC);
            #pragma unroll
            for (int b = 0; b < BB; ++b) {
                const float2 vA = unpack2(accA[b]);
                const float2 vB = unpack2(accB[b]);
                rw[b * GC + colA] = vA.x + vA.y;
                rw[b * GC + colB] = vB.x + vB.y;
            }
        }
        __syncthreads();   // S3: partials ready

        // Phase 5: cross-slice reduction -> gate preactivations gsm[b][gc].
        // 512 outputs, 256 threads: 2 columns each.
        #pragma unroll
        for (int r = 0; r < 2; ++r) {
            const int idx = tid + r * NTHREADS;
            float s = 0.f;
            #pragma unroll
            for (int ss = 0; ss < NSLICE; ++ss) s += red[ss * (BB * GC) + idx];
            gsm[idx] = s;
        }
        __syncthreads();   // S4: gsm ready

        // Phase 6: elementwise LSTM cell update + global writes.
        if (tid < BB * DPC) {
            const int base = cb * GC + cd;            // gc = g*8 + dl
            const float gi = gsm[base +  0] + wxi + b_i;
            const float gf = gsm[base +  8] + wxf + b_f;
            const float gz = gsm[base + 16] + wxz + b_z;
            const float go = gsm[base + 24] + wxo + b_o;
            const float i_ = 1.f / (1.f + __expf(-gi));
            const float f_ = 1.f / (1.f + __expf(-gf));
            const float z_ = tanhf(gz);
            const float o_ = 1.f / (1.f + __expf(-go));
            const float cn = f_ * c_state + i_ * z_;
            const float hn = o_ * tanhf(cn);
            c_state = cn;
            const int d = d0 + cd;
            out[((size_t)(0 * BB + cb) * (TT + 1) + (t + 1)) * DD + d] = hn;
            out[((size_t)(1 * BB + cb) * (TT + 1) + (t + 1)) * DD + d] = cn;
            g_hbuf[(t + 1) & 1][cb * DD + d] = hn;    // exchange (double-buffered)
        }

        // Phase 7: software grid barrier with release/acquire scoped ops.
        // All 96 CTAs are co-resident -> no deadlock.
        __syncthreads();                   // all global writes issued
        if (tid == 0) {
            asm volatile("st.release.gpu.global.u32 [%0], %1;"
                         :: "l"(&g_flags[cta]), "r"((unsigned)(t + 1)) : "memory");
        }
        if (tid < NCTA) {
            unsigned v;
            do {
                asm volatile("ld.acquire.gpu.global.u32 %0, [%1];"
                             : "=r"(v) : "l"(&g_flags[tid]) : "memory");
            } while (v < (unsigned)(t + 1));
        }
        __syncthreads();                   // CTA-scope fence propagates acquire
    }
}

extern "C" void kernel_launch(void* const* d_in, const int* in_sizes, int n_in,
                              void* d_out, int out_size)
{
    const float* states = (const float*)d_in[0];  // [2,16,1,768]
    const float* Wx     = (const float*)d_in[1];  // [16,1024,4,1,768]
    const float* R      = (const float*)d_in[2];  // [4,1,768,768]
    const float* bias   = (const float*)d_in[3];  // [4,1,768]
    float*       out    = (float*)d_out;          // [2,16,1025,1,768]

    const size_t smem_bytes = (size_t)BB * DD * sizeof(float);  // 49152 = 48KB

    rnn_reset_kernel<<<1, 128>>>();
    rnn_persistent_kernel<<<NCTA, NTHREADS, smem_bytes>>>(states, Wx, R, bias, out);
}

// round 5
// speedup vs baseline: 1.6051x; 1.6051x over previous
#include <cuda_runtime.h>
#include <cstdint>

// Problem constants  (byte-exact R1 structure; only the barrier differs)
#define NCTA      96     // persistent CTAs (<= 148 SMs, all co-resident)
#define NTHREADS  256    // 8 warps — proven best shape (R1)
#define BB        16     // batch
#define TT        1024   // time steps
#define DD        768    // hidden dim
#define NGATES    4
#define DPC       8      // d-columns per CTA (96*8 = 768)
#define GC        32     // gate columns per CTA (4 gates * 8 d)
#define NW        8      // warps per CTA (K-split)
#define KS        96     // k per warp (8*96 = 768)
#define KS2       48     // packed f32x2 pairs per warp

// Global exchange state (device globals: no allocation anywhere)
__device__ __align__(16) float    g_hbuf[2][BB * DD];
__device__ unsigned               g_ctr;      // monotonic arrival counter

static __device__ __forceinline__ unsigned long long pack2(float x, float y) {
    unsigned long long r;
    asm("mov.b64 %0, {%1, %2};" : "=l"(r) : "f"(x), "f"(y));
    return r;
}
static __device__ __forceinline__ void fma2(unsigned long long& d,
                                            unsigned long long a,
                                            unsigned long long b) {
    // Packed dual-FMA (Blackwell f32x2) — 2x FFMA throughput vs scalar.
    asm("fma.rn.f32x2 %0, %1, %2, %0;" : "+l"(d) : "l"(a), "l"(b));
}
static __device__ __forceinline__ float2 unpack2(unsigned long long v) {
    float lo, hi;
    asm("mov.b64 {%0, %1}, %2;" : "=f"(lo), "=f"(hi) : "l"(v));
    return make_float2(lo, hi);
}

// Zero the barrier counter before each run (graph replays reuse device globals).
__global__ void rnn_reset_kernel() {
    if (threadIdx.x == 0) g_ctr = 0u;
}

__global__ void __launch_bounds__(NTHREADS, 1)
rnn_persistent_kernel(const float* __restrict__ states,
                      const float* __restrict__ Wx,
                      const float* __restrict__ R,
                      const float* __restrict__ bias,
                      float* __restrict__ out)
{
    // Dynamic smem = 48KB exactly (h panel). Reduction scratch ALIASES the h
    // panel: h is dead after the GEMM phase (extra __syncthreads guards it).
    extern __shared__ float smem[];
    float* h_sm = smem;                    // [BB][DD]   (phases 2-3)
    float* red  = smem;                    // [NW][BB][GC] = 4096 floats (phases 4-5)
    float* gsm  = smem + NW * BB * GC;     // [BB][GC]   = 512 floats    (phases 5-6)

    const int tid = threadIdx.x;
    const int cta = blockIdx.x;
    const int w   = tid >> 5;      // warp id -> k-slice
    const int l   = tid & 31;      // lane -> gate column
    const int gg  = l >> 3;        // gate index 0..3
    const int dl  = l & 7;         // local d column 0..7
    const int d0  = cta * DPC;

    // ---- One-time: R slice into registers, packed in k-pairs. Reused 1024x. ----
    unsigned long long R2[KS2];
    {
        // R layout: [NG][NH=1][D][D] -> R[g][k][d]
        const float* Rg = R + (size_t)gg * DD * DD + (size_t)(d0 + dl);
        const int kb = w * KS;
        #pragma unroll
        for (int j = 0; j < KS2; ++j) {
            float a = Rg[(size_t)(kb + 2 * j)     * DD];
            float b = Rg[(size_t)(kb + 2 * j + 1) * DD];
            R2[j] = pack2(a, b);
        }
    }

    // ---- One-time: per-cell state (c), biases, and t=0 output row. ----
    float c_state = 0.f, b_i = 0.f, b_f = 0.f, b_z = 0.f, b_o = 0.f;
    int cb = 0, cd = 0;
    if (tid < BB * DPC) {                         // 128 "cell" threads
        cb = tid >> 3;                            // batch
        cd = tid & 7;                             // local d
        const int d = d0 + cd;
        b_i = bias[0 * DD + d];
        b_f = bias[1 * DD + d];
        b_z = bias[2 * DD + d];
        b_o = bias[3 * DD + d];
        const float h0 = states[(size_t)(0 * BB + cb) * DD + d];
        c_state        = states[(size_t)(1 * BB + cb) * DD + d];
        // out layout: [2][B][T+1][NH=1][D]; row t=0 is the initial state.
        out[((size_t)(0 * BB + cb) * (TT + 1) + 0) * DD + d] = h0;
        out[((size_t)(1 * BB + cb) * (TT + 1) + 0) * DD + d] = c_state;
    }

    // ---- Main recurrence ----
    for (int t = 0; t < TT; ++t) {
        // Phase 1: prefetch Wx(t) for this CTA's cells (hidden behind GEMM).
        float wxi = 0.f, wxf = 0.f, wxz = 0.f, wxo = 0.f;
        if (tid < BB * DPC) {
            const float* wp = Wx + ((size_t)cb * TT + t) * (NGATES * DD) + (d0 + cd);
            wxi = wp[0 * DD];
            wxf = wp[1 * DD];
            wxz = wp[2 * DD];
            wxo = wp[3 * DD];
        }

        // Phase 2: load h(t) panel [16 x 768] into smem (coalesced float4).
        {
            const float* src = (t == 0) ? states : g_hbuf[t & 1];
            const float4* s4 = (const float4*)src;
            float4* d4 = (float4*)h_sm;
            #pragma unroll
            for (int r = 0; r < (BB * DD / 4) / NTHREADS; ++r)   // 12 iters
                d4[tid + r * NTHREADS] = s4[tid + r * NTHREADS];
        }
        __syncthreads();   // S1: h panel ready

        // Phase 3: GEMM. Lane owns gate-column (gg,dl); warp owns k-slice.
        // R from registers, h via broadcast LDS.128, packed dual-FMA.
        unsigned long long acc[BB];
        #pragma unroll
        for (int b = 0; b < BB; ++b) acc[b] = 0ull;   // (0.f, 0.f)
        {
            const int kb = w * KS;
            #pragma unroll
            for (int j = 0; j < KS2; j += 2) {        // 4 k's per iter
                #pragma unroll
                for (int b = 0; b < BB; ++b) {
                    const ulonglong2 hh =
                        *(const ulonglong2*)(h_sm + (size_t)b * DD + kb + 2 * j);
                    fma2(acc[b], hh.x, R2[j]);
                    fma2(acc[b], hh.y, R2[j + 1]);
                }
            }
        }
        __syncthreads();   // S2: all warps done reading h_sm (red aliases it!)

        // Phase 4: spill per-warp partials. red[w][b][gc]: lanes write
        // consecutive gc -> conflict-free.
        {
            float* rw = red + (size_t)w * (BB * GC);
            #pragma unroll
            for (int b = 0; b < BB; ++b) {
                const float2 v = unpack2(acc[b]);
                rw[b * GC + l] = v.x + v.y;   // fold even/odd partial sums
            }
        }
        __syncthreads();   // S3: partials ready

        // Phase 5: cross-warp reduction -> gate preactivations gsm[b][gc].
        #pragma unroll
        for (int r = 0; r < 2; ++r) {
            const int idx = tid + r * NTHREADS;       // 512 gate columns total
            float s = 0.f;
            #pragma unroll
            for (int ww = 0; ww < NW; ++ww) s += red[ww * (BB * GC) + idx];
            gsm[idx] = s;
        }
        __syncthreads();   // S4: gsm ready

        // Phase 6: elementwise LSTM cell update + global writes.
        if (tid < BB * DPC) {
            const int base = cb * GC + cd;            // gc = g*8 + dl
            const float gi = gsm[base +  0] + wxi + b_i;
            const float gf = gsm[base +  8] + wxf + b_f;
            const float gz = gsm[base + 16] + wxz + b_z;
            const float go = gsm[base + 24] + wxo + b_o;
            const float i_ = 1.f / (1.f + __expf(-gi));
            const float f_ = 1.f / (1.f + __expf(-gf));
            const float z_ = tanhf(gz);
            const float o_ = 1.f / (1.f + __expf(-go));
            const float cn = f_ * c_state + i_ * z_;
            const float hn = o_ * tanhf(cn);
            c_state = cn;
            const int d = d0 + cd;
            out[((size_t)(0 * BB + cb) * (TT + 1) + (t + 1)) * DD + d] = hn;
            out[((size_t)(1 * BB + cb) * (TT + 1) + (t + 1)) * DD + d] = cn;
            g_hbuf[(t + 1) & 1][cb * DD + d] = hn;    // exchange (double-buffered)
        }

        // Phase 7: grid barrier — single monotonic counter.
        // Arrive: one REDG-rate atomicAdd per CTA after a release fence.
        // Wait: ONE spinning load per CTA on ONE cache line (96 chip-wide,
        // vs 9216 flag-poll loads before) -> no L2 pollution of the
        // critical-path h/Wx loads. All 96 CTAs co-resident -> no deadlock.
        __syncthreads();                   // all global writes issued
        if (tid == 0) {
            __threadfence();               // make h/out writes GPU-visible
            atomicAdd(&g_ctr, 1u);
            const unsigned target = (unsigned)(NCTA) * (unsigned)(t + 1);
            volatile unsigned* f = &g_ctr;
            while (*f < target) { }
            __threadfence();               // acquire
        }
        __syncthreads();                   // whole CTA may proceed
    }
}

extern "C" void kernel_launch(void* const* d_in, const int* in_sizes, int n_in,
                              void* d_out, int out_size)
{
    const float* states = (const float*)d_in[0];  // [2,16,1,768]
    const float* Wx     = (const float*)d_in[1];  // [16,1024,4,1,768]
    const float* R      = (const float*)d_in[2];  // [4,1,768,768]
    const float* bias   = (const float*)d_in[3];  // [4,1,768]
    float*       out    = (float*)d_out;          // [2,16,1025,1,768]

    const size_t smem_bytes = (size_t)BB * DD * sizeof(float);  // 49152 = 48KB

    rnn_reset_kernel<<<1, 32>>>();
    rnn_persistent_kernel<<<NCTA, NTHREADS, smem_bytes>>>(states, Wx, R, bias, out);
}

// round 6
// speedup vs baseline: 1.8502x; 1.1527x over previous
#include <cuda_runtime.h>
#include <cstdint>

// Problem constants
#define NCTA      96     // persistent CTAs (<= 148 SMs, all co-resident)
#define NTHREADS  256    // 8 warps — proven best shape
#define BB        16     // batch
#define TT        1024   // time steps
#define DD        768    // hidden dim
#define NGATES    4
#define DPC       8      // d-columns per CTA (96*8 = 768)
#define GC        32     // gate columns per CTA (interleaved: gc = dl*4 + gate)
#define NSLICE    16     // k-slices = 8 warps x 2 half-warps
#define KS        48     // k per slice (16*48 = 768)
#define KS2       24     // packed f32x2 k-pairs per slice
#define REDPITCH  520    // padded floats per slice row (conflict-free spill)

// Global exchange state (device globals: no allocation anywhere)
__device__ __align__(16) float    g_hbuf[2][BB * DD];
__device__ unsigned               g_ctr;      // monotonic arrival counter

static __device__ __forceinline__ unsigned long long pack2(float x, float y) {
    unsigned long long r;
    asm("mov.b64 %0, {%1, %2};" : "=l"(r) : "f"(x), "f"(y));
    return r;
}
static __device__ __forceinline__ void fma2(unsigned long long& d,
                                            unsigned long long a,
                                            unsigned long long b) {
    // Packed dual-FMA (Blackwell f32x2) — 2x FFMA throughput vs scalar.
    asm("fma.rn.f32x2 %0, %1, %2, %0;" : "+l"(d) : "l"(a), "l"(b));
}
static __device__ __forceinline__ float2 unpack2(unsigned long long v) {
    float lo, hi;
    asm("mov.b64 {%0, %1}, %2;" : "=f"(lo), "=f"(hi) : "l"(v));
    return make_float2(lo, hi);
}

// Zero the barrier counter before each run (graph replays reuse device globals).
__global__ void rnn_reset_kernel() {
    if (threadIdx.x == 0) g_ctr = 0u;
}

__global__ void __launch_bounds__(NTHREADS, 1)
rnn_persistent_kernel(const float* __restrict__ states,
                      const float* __restrict__ Wx,
                      const float* __restrict__ R,
                      const float* __restrict__ bias,
                      float* __restrict__ out)
{
    // Dynamic smem = 48KB (h panel). red (16*520 = 8320 floats) ALIASES the h
    // panel: h is dead after the GEMM phase (S2 guards it), and next-step h
    // loads happen only after the grid barrier (so red reads are done).
    extern __shared__ float smem[];
    float* h_sm = smem;                    // [BB][DD] = 12288 floats (GEMM phase)
    float* red  = smem;                    // [NSLICE][REDPITCH]     (reduce phase)

    const int tid = threadIdx.x;
    const int cta = blockIdx.x;
    const int w   = tid >> 5;        // warp id (0..7)
    const int l   = tid & 31;        // lane
    const int hw  = l >> 4;          // half-warp -> k sub-slice
    const int c   = l & 15;          // column-pair index (0..15)
    const int sl  = (w << 1) | hw;   // k-slice id (0..15)
    const int kb  = sl * KS;         // k base for this slice
    const int gcA = c;               // interleaved gate-col: gg = gc&3, dl = gc>>2
    const int gcB = c + 16;
    const int d0  = cta * DPC;

    // ---- One-time: R slices for BOTH columns into registers (k-pair packed).
    unsigned long long RA[KS2], RB[KS2];   // 96 registers
    {
        const float* RgA = R + (size_t)(gcA & 3) * DD * DD + (size_t)(d0 + (gcA >> 2));
        const float* RgB = R + (size_t)(gcB & 3) * DD * DD + (size_t)(d0 + (gcB >> 2));
        #pragma unroll
        for (int j = 0; j < KS2; ++j) {
            RA[j] = pack2(RgA[(size_t)(kb + 2 * j) * DD],
                          RgA[(size_t)(kb + 2 * j + 1) * DD]);
            RB[j] = pack2(RgB[(size_t)(kb + 2 * j) * DD],
                          RgB[(size_t)(kb + 2 * j + 1) * DD]);
        }
    }

    // ---- One-time: per-cell state (c), biases, and t=0 output row. ----
    float c_state = 0.f, b_i = 0.f, b_f = 0.f, b_z = 0.f, b_o = 0.f;
    int cb = 0, cd = 0;
    if (tid < BB * DPC) {                         // 128 "cell" threads
        cb = tid >> 3;                            // batch
        cd = tid & 7;                             // local d
        const int d = d0 + cd;
        b_i = bias[0 * DD + d];
        b_f = bias[1 * DD + d];
        b_z = bias[2 * DD + d];
        b_o = bias[3 * DD + d];
        const float h0 = states[(size_t)(0 * BB + cb) * DD + d];
        c_state        = states[(size_t)(1 * BB + cb) * DD + d];
        // out layout: [2][B][T+1][NH=1][D]; row t=0 is the initial state.
        out[((size_t)(0 * BB + cb) * (TT + 1) + 0) * DD + d] = h0;
        out[((size_t)(1 * BB + cb) * (TT + 1) + 0) * DD + d] = c_state;
    }

    // ---- Main recurrence ----
    for (int t = 0; t < TT; ++t) {
        // Phase 1: issue Wx(t) loads early (consumed in cell phase).
        float wxi = 0.f, wxf = 0.f, wxz = 0.f, wxo = 0.f;
        if (tid < BB * DPC) {
            const float* wp = Wx + ((size_t)cb * TT + t) * (NGATES * DD) + (d0 + cd);
            wxi = wp[0 * DD];
            wxf = wp[1 * DD];
            wxz = wp[2 * DD];
            wxo = wp[3 * DD];
        }

        // Phase 2: WARP-LOCAL h slice load — warp w only needs k in
        // [w*96, w*96+96). No CTA barrier; __syncwarp suffices.
        {
            const float4* s4 = (const float4*)((t == 0) ? states : g_hbuf[t & 1]);
            float4* d4 = (float4*)h_sm;
            #pragma unroll
            for (int r = 0; r < 12; ++r) {            // 384 float4 per warp
                const int local = r * 32 + l;         // 0..383
                const int b  = local / 24;            // 24 float4 per batch row
                const int kq = local - b * 24;
                const int idx = b * (DD / 4) + w * 24 + kq;
                d4[idx] = s4[idx];
            }
            __syncwarp();
        }

        // Phase 3: GEMM. Half-warp owns 48-k slice; lane owns 2 gate columns.
        // One LDS.128 (4 h, half-warp broadcast) feeds 4 FFMA2.
        unsigned long long accA[BB], accB[BB];        // 64 registers
        #pragma unroll
        for (int b = 0; b < BB; ++b) { accA[b] = 0ull; accB[b] = 0ull; }
        {
            const float* hk = h_sm + kb;
            #pragma unroll
            for (int j = 0; j < KS2; j += 2) {        // 12 iters, 4 k each
                #pragma unroll
                for (int b = 0; b < BB; ++b) {
                    const ulonglong2 hh =
                        *(const ulonglong2*)(hk + (size_t)b * DD + 2 * j);
                    fma2(accA[b], hh.x, RA[j]);
                    fma2(accA[b], hh.y, RA[j + 1]);
                    fma2(accB[b], hh.x, RB[j]);
                    fma2(accB[b], hh.y, RB[j + 1]);
                }
            }
        }
        __syncthreads();   // S2: all warps done reading h_sm (red aliases it!)

        // Phase 4: spill per-slice partials red[sl][b*32+gc] (fold even/odd k).
        // REDPITCH=520 pads slices apart -> conflict-free across half-warps.
        {
            float* rw = red + (size_t)sl * REDPITCH;
            #pragma unroll
            for (int b = 0; b < BB; ++b) {
                const float2 vA = unpack2(accA[b]);
                const float2 vB = unpack2(accB[b]);
                rw[b * GC + gcA] = vA.x + vA.y;
                rw[b * GC + gcB] = vB.x + vB.y;
            }
        }
        __syncthreads();   // S3: partials ready

        // Phase 5+6 fused: cell threads reduce their own 4 gates directly
        // (interleaved gc -> one float4 per slice) and run the LSTM update.
        if (tid < BB * DPC) {
            float4 g = make_float4(0.f, 0.f, 0.f, 0.f);
            const int off = cb * GC + cd * 4;         // gates i,f,z,o contiguous
            #pragma unroll
            for (int ss = 0; ss < NSLICE; ++ss) {
                const float4 p = *(const float4*)(red + (size_t)ss * REDPITCH + off);
                g.x += p.x; g.y += p.y; g.z += p.z; g.w += p.w;
            }
            const float gi = g.x + wxi + b_i;
            const float gf = g.y + wxf + b_f;
            const float gz = g.z + wxz + b_z;
            const float go = g.w + wxo + b_o;
            const float i_ = 1.f / (1.f + __expf(-gi));
            const float f_ = 1.f / (1.f + __expf(-gf));
            const float z_ = tanhf(gz);
            const float o_ = 1.f / (1.f + __expf(-go));
            const float cn = f_ * c_state + i_ * z_;
            const float hn = o_ * tanhf(cn);
            c_state = cn;
            const int d = d0 + cd;
            out[((size_t)(0 * BB + cb) * (TT + 1) + (t + 1)) * DD + d] = hn;
            out[((size_t)(1 * BB + cb) * (TT + 1) + (t + 1)) * DD + d] = cn;
            g_hbuf[(t + 1) & 1][cb * DD + d] = hn;    // exchange (double-buffered)
        }

        // Phase 7: grid barrier — single monotonic counter, volatile poll
        // (proven fast in R1/R5; ld.acquire variant measured ~3us/step slower).
        __syncthreads();                   // all global writes issued
        if (tid == 0) {
            __threadfence();               // make h/out writes GPU-visible
            atomicAdd(&g_ctr, 1u);
            const unsigned target = (unsigned)(NCTA) * (unsigned)(t + 1);
            volatile unsigned* f = &g_ctr;
            while (*f < target) { }
            __threadfence();               // acquire
        }
        __syncthreads();                   // whole CTA may proceed
    }
}

extern "C" void kernel_launch(void* const* d_in, const int* in_sizes, int n_in,
                              void* d_out, int out_size)
{
    const float* states = (const float*)d_in[0];  // [2,16,1,768]
    const float* Wx     = (const float*)d_in[1];  // [16,1024,4,1,768]
    const float* R      = (const float*)d_in[2];  // [4,1,768,768]
    const float* bias   = (const float*)d_in[3];  // [4,1,768]
    float*       out    = (float*)d_out;          // [2,16,1025,1,768]

    const size_t smem_bytes = (size_t)BB * DD * sizeof(float);  // 49152 = 48KB

    rnn_reset_kernel<<<1, 32>>>();
    rnn_persistent_kernel<<<NCTA, NTHREADS, smem_bytes>>>(states, Wx, R, bias, out);
}